// round 1
// baseline (speedup 1.0000x reference)
#include <cuda_runtime.h>
#include <math.h>

// PPCA gating layer, GB300 sm_103a.
// x: [B=64, C=256, H=56, W=56] fp32, weight: [HW=3136, 15] fp32.
// out[b,c,s] = x[b,c,s] * sigmoid( sum_f (feat[f]-mu)/sigma * weight[s,f] )
// feats = channel-group means at scales (1,2,4,8) -> 15 values, built from
// 8 partial sums of 32-channel groups.

#define BATCH   64
#define CH      256
#define HW      3136
#define TILE_S  64
#define NTHR    512   // 64 spatial x 8 channel-groups

__global__ __launch_bounds__(NTHR, 3)
void ppca_gate_kernel(const float* __restrict__ x,
                      const float* __restrict__ weight,
                      float* __restrict__ out)
{
    extern __shared__ float sm[];
    float* sx    = sm;                       // [256][64] tile of x
    float* sgrp  = sm + CH * TILE_S;         // [8][64] group sums
    float* sgate = sgrp + 8 * TILE_S;        // [64] gates

    const int s0 = blockIdx.x * TILE_S;      // 49 tiles * 64 = 3136
    const int b  = blockIdx.y;

    const int t  = threadIdx.x;
    const int sl = t & (TILE_S - 1);         // spatial within tile
    const int g  = t >> 6;                   // channel group 0..7

    const size_t base = (size_t)b * CH * HW + (size_t)s0 + sl;
    const float* xb = x + base;

    // ---- Pass 1: stream 32 channels of group g, stage in smem, accumulate ----
    float sum = 0.0f;
    #pragma unroll
    for (int cc = 0; cc < 32; cc++) {
        const int c = g * 32 + cc;
        float v = __ldg(xb + (size_t)c * HW);
        sx[c * TILE_S + sl] = v;
        sum += v;
    }
    sgrp[g * TILE_S + sl] = sum;
    __syncthreads();

    // ---- Gate computation: one thread per spatial location ----
    if (t < TILE_S) {
        float S8[8];
        #pragma unroll
        for (int j = 0; j < 8; j++) S8[j] = sgrp[j * TILE_S + t];

        float S4[4], S2[2], S1;
        #pragma unroll
        for (int j = 0; j < 4; j++) S4[j] = S8[2*j] + S8[2*j+1];
        S2[0] = S4[0] + S4[1];
        S2[1] = S4[2] + S4[3];
        S1    = S2[0] + S2[1];

        // feats in reference concat order: [scale1, scale2, scale4, scale8]
        float f[15];
        f[0] = S1 * (1.0f / 256.0f);
        f[1] = S2[0] * (1.0f / 128.0f);
        f[2] = S2[1] * (1.0f / 128.0f);
        #pragma unroll
        for (int j = 0; j < 4; j++) f[3 + j] = S4[j] * (1.0f / 64.0f);
        #pragma unroll
        for (int j = 0; j < 8; j++) f[7 + j] = S8[j] * (1.0f / 32.0f);

        float mu = 0.0f;
        #pragma unroll
        for (int j = 0; j < 15; j++) mu += f[j];
        mu *= (1.0f / 15.0f);

        float var = 0.0f;
        #pragma unroll
        for (int j = 0; j < 15; j++) {
            float d = f[j] - mu;
            var += d * d;
        }
        var *= (1.0f / 15.0f);
        const float inv_std = rsqrtf(var);

        const float* wr = weight + (size_t)(s0 + t) * 15;
        float z = 0.0f;
        #pragma unroll
        for (int j = 0; j < 15; j++)
            z += (f[j] - mu) * __ldg(wr + j);
        z *= inv_std;

        sgate[t] = 1.0f / (1.0f + expf(-z));
    }
    __syncthreads();

    // ---- Pass 2: write x * gate from smem (no HBM re-read) ----
    const float gate = sgate[sl];
    float* ob = out + base;
    #pragma unroll
    for (int cc = 0; cc < 32; cc++) {
        const int c = g * 32 + cc;
        ob[(size_t)c * HW] = sx[c * TILE_S + sl] * gate;
    }
}

extern "C" void kernel_launch(void* const* d_in, const int* in_sizes, int n_in,
                              void* d_out, int out_size)
{
    const float* x      = (const float*)d_in[0];
    const float* weight = (const float*)d_in[1];
    float* out          = (float*)d_out;

    const int smem_bytes = (CH * TILE_S + 8 * TILE_S + TILE_S) * (int)sizeof(float); // 67840
    cudaFuncSetAttribute(ppca_gate_kernel,
                         cudaFuncAttributeMaxDynamicSharedMemorySize, smem_bytes);

    dim3 grid(HW / TILE_S, BATCH);   // (49, 64)
    ppca_gate_kernel<<<grid, NTHR, smem_bytes>>>(x, weight, out);
}

// round 2
// speedup vs baseline: 1.0626x; 1.0626x over previous
#include <cuda_runtime.h>
#include <math.h>

// PPCA gating layer, GB300 sm_103a — round 2: no smem staging, L2 re-read.
// x: [B=64, C=256, H=56, W=56] fp32, weight: [HW=3136, 15] fp32.
// out[b,c,s] = x[b,c,s] * sigmoid( sum_f (feat[f]-mu)/sigma * weight[s,f] )
//
// Pass 1: each thread (spatial sl, group g) sums its 32 channels (DRAM read).
// Gate:   64 threads build the 15 multi-scale feats from 8 group sums,
//         normalize (ddof=0), dot with weight, sigmoid.
// Pass 2: re-read the same 32 channels (L2-resident: live set ~28MB << 126MB
//         L2, CTA lifetime < eviction horizon) and write x * gate.
// smem = 2.3KB -> 4 CTAs/SM -> 100% occupancy to hide latency/phase gaps.

#define BATCH   64
#define CH      256
#define HW      3136
#define TILE_S  64
#define NTHR    512   // 64 spatial x 8 channel-groups

__global__ __launch_bounds__(NTHR, 4)
void ppca_gate_kernel(const float* __restrict__ x,
                      const float* __restrict__ weight,
                      float* __restrict__ out)
{
    __shared__ float sgrp[8 * TILE_S];   // group sums
    __shared__ float sgate[TILE_S];      // gates

    const int s0 = blockIdx.x * TILE_S;  // 49 tiles * 64 = 3136
    const int b  = blockIdx.y;

    const int t  = threadIdx.x;
    const int sl = t & (TILE_S - 1);     // spatial within tile
    const int g  = t >> 6;               // channel group 0..7

    const size_t base = (size_t)b * CH * HW + (size_t)s0 + sl;
    const float* xb = x + base + (size_t)(g * 32) * HW;

    // ---- Pass 1: stream 32 channels of group g, accumulate only ----
    float sum = 0.0f;
    #pragma unroll
    for (int cc = 0; cc < 32; cc++) {
        sum += __ldg(xb + (size_t)cc * HW);
    }
    sgrp[g * TILE_S + sl] = sum;
    __syncthreads();

    // ---- Gate computation: one thread per spatial location ----
    if (t < TILE_S) {
        float S8[8];
        #pragma unroll
        for (int j = 0; j < 8; j++) S8[j] = sgrp[j * TILE_S + t];

        float S4[4], S2[2], S1;
        #pragma unroll
        for (int j = 0; j < 4; j++) S4[j] = S8[2*j] + S8[2*j+1];
        S2[0] = S4[0] + S4[1];
        S2[1] = S4[2] + S4[3];
        S1    = S2[0] + S2[1];

        // feats in reference concat order: [scale1, scale2, scale4, scale8]
        float f[15];
        f[0] = S1 * (1.0f / 256.0f);
        f[1] = S2[0] * (1.0f / 128.0f);
        f[2] = S2[1] * (1.0f / 128.0f);
        #pragma unroll
        for (int j = 0; j < 4; j++) f[3 + j] = S4[j] * (1.0f / 64.0f);
        #pragma unroll
        for (int j = 0; j < 8; j++) f[7 + j] = S8[j] * (1.0f / 32.0f);

        float mu = 0.0f;
        #pragma unroll
        for (int j = 0; j < 15; j++) mu += f[j];
        mu *= (1.0f / 15.0f);

        float var = 0.0f;
        #pragma unroll
        for (int j = 0; j < 15; j++) {
            float d = f[j] - mu;
            var += d * d;
        }
        var *= (1.0f / 15.0f);
        const float inv_std = rsqrtf(var);

        const float* wr = weight + (size_t)(s0 + t) * 15;
        float z = 0.0f;
        #pragma unroll
        for (int j = 0; j < 15; j++)
            z += (f[j] - mu) * __ldg(wr + j);
        z *= inv_std;

        sgate[t] = 1.0f / (1.0f + expf(-z));
    }
    __syncthreads();

    // ---- Pass 2: re-read (L2 hit) and write x * gate ----
    const float gate = sgate[sl];
    float* ob = out + base + (size_t)(g * 32) * HW;
    #pragma unroll
    for (int cc = 0; cc < 32; cc++) {
        const size_t off = (size_t)cc * HW;
        ob[off] = __ldg(xb + off) * gate;
    }
}

extern "C" void kernel_launch(void* const* d_in, const int* in_sizes, int n_in,
                              void* d_out, int out_size)
{
    const float* x      = (const float*)d_in[0];
    const float* weight = (const float*)d_in[1];
    float* out          = (float*)d_out;

    dim3 grid(HW / TILE_S, BATCH);   // (49, 64)
    ppca_gate_kernel<<<grid, NTHR>>>(x, weight, out);
}